// round 5
// baseline (speedup 1.0000x reference)
#include <cuda_runtime.h>
#include <math.h>

// Problem constants (fixed by the reference)
#define S_LEN   1024
#define I_DIM   1024
#define H_DIM   2048
#define L_NUM   4

#define SCAN_CTAS     128
#define ROWS_PER_CTA  16              // H_DIM / SCAN_CTAS
#define SCAN_THREADS  128             // 4 warps, 4 rows per warp
#define SCAN_SMEM_BYTES (ROWS_PER_CTA * H_DIM * (int)sizeof(float))  // 131072 (weights only)

// Scratch (device globals — no allocation allowed)
__device__ float g_U [S_LEN * H_DIM];   // u_l(t) for current layer (8 MB)
__device__ float g_HA[S_LEN * H_DIM];   // hidden states of current layer (8 MB)
__device__ int   g_cnt[S_LEN];          // one arrival counter per timestep

// ---------------------------------------------------------------------------
// Memory-model helpers. The arrival counter is accessed ONLY with morally
// strong ops (red.relaxed.gpu / ld.relaxed.gpu) + acq_rel fences, which per
// the PTX memory model forms a valid release->acquire edge for the weak h
// stores/loads around them.
// ---------------------------------------------------------------------------
__device__ __forceinline__ int ld_relaxed_gpu(const int* p) {
    int v;
    asm volatile("ld.relaxed.gpu.global.s32 %0, [%1];" : "=r"(v) : "l"(p) : "memory");
    return v;
}
__device__ __forceinline__ void fence_gpu() {
    asm volatile("fence.acq_rel.gpu;" ::: "memory");
}
__device__ __forceinline__ void red_add_gpu(int* p) {
    asm volatile("red.relaxed.gpu.global.add.s32 [%0], 1;" :: "l"(p) : "memory");
}

// ---------------------------------------------------------------------------
// GEMM: C[M,N] = A[M,K] @ B[N,K]^T + bias1[n] + bias2[n]
// 128x128 tile, BK=8, 256 threads, 8x8 per-thread microtile. (Unchanged; proven.)
// ---------------------------------------------------------------------------
__global__ void gemm_bias_kernel(const float* __restrict__ A,
                                 const float* __restrict__ B,
                                 float* __restrict__ C,
                                 const float* __restrict__ bias1,
                                 const float* __restrict__ bias2,
                                 int M, int N, int K)
{
    __shared__ float As[8][128];
    __shared__ float Bs[8][128];

    const int tid = threadIdx.x;
    const int bm  = blockIdx.y * 128;
    const int bn  = blockIdx.x * 128;

    const int loadRow = tid >> 1;        // 0..127
    const int loadCol = (tid & 1) * 4;   // 0 or 4

    const int tx = tid & 15;             // n sub-tile
    const int ty = tid >> 4;             // m sub-tile

    float acc[8][8];
#pragma unroll
    for (int i = 0; i < 8; i++)
#pragma unroll
        for (int j = 0; j < 8; j++) acc[i][j] = 0.f;

    const float* Ag = A + (size_t)(bm + loadRow) * K + loadCol;
    const float* Bg = B + (size_t)(bn + loadRow) * K + loadCol;

    for (int k0 = 0; k0 < K; k0 += 8) {
        float4 av = *(const float4*)(Ag + k0);
        float4 bv = *(const float4*)(Bg + k0);
        As[loadCol + 0][loadRow] = av.x;
        As[loadCol + 1][loadRow] = av.y;
        As[loadCol + 2][loadRow] = av.z;
        As[loadCol + 3][loadRow] = av.w;
        Bs[loadCol + 0][loadRow] = bv.x;
        Bs[loadCol + 1][loadRow] = bv.y;
        Bs[loadCol + 2][loadRow] = bv.z;
        Bs[loadCol + 3][loadRow] = bv.w;
        __syncthreads();

#pragma unroll
        for (int k = 0; k < 8; k++) {
            float a[8], b[8];
#pragma unroll
            for (int i = 0; i < 8; i++) a[i] = As[k][ty * 8 + i];
#pragma unroll
            for (int j = 0; j < 8; j++) b[j] = Bs[k][tx * 8 + j];
#pragma unroll
            for (int i = 0; i < 8; i++)
#pragma unroll
                for (int j = 0; j < 8; j++)
                    acc[i][j] += a[i] * b[j];
        }
        __syncthreads();
    }

    // Epilogue with fused bias add, float4 stores
#pragma unroll
    for (int i = 0; i < 8; i++) {
        const int m = bm + ty * 8 + i;
        float* crow = C + (size_t)m * N + bn + tx * 8;
#pragma unroll
        for (int j = 0; j < 8; j += 4) {
            const int n = bn + tx * 8 + j;
            float4 v;
            v.x = acc[i][j + 0] + bias1[n + 0] + bias2[n + 0];
            v.y = acc[i][j + 1] + bias1[n + 1] + bias2[n + 1];
            v.z = acc[i][j + 2] + bias1[n + 2] + bias2[n + 2];
            v.w = acc[i][j + 3] + bias1[n + 3] + bias2[n + 3];
            *(float4*)(crow + j) = v;
        }
    }
}

// ---------------------------------------------------------------------------
// Persistent scan: h(t) = tanh(U[t] + Wh @ h(t-1)) over t = 0..S-1.
// Wh (H x H) lives sliced across 128 CTAs' SMEM (16 rows each).
// Per-step handshake (R2-proven ordering + low-latency detection):
//   producer: st.cg h rows -> fence (IN the storing thread) -> __syncthreads
//             -> tid0: red.relaxed.gpu on cnt[t]
//   consumer: EVERY thread polls ld.relaxed.gpu on cnt[t-1] until it reaches
//             128*(layer+1), then a per-thread acquire fence, then streams
//             h(t-1) from L2 (__ldcg, 2-deep prefetch) under the SMEM
//             weight-read stream. No consumer-side barrier.
// ---------------------------------------------------------------------------
__global__ void __launch_bounds__(SCAN_THREADS, 1)
scan_kernel(const float* __restrict__ Wh,    // layer's H x H row-major slice base
            const float* __restrict__ U,     // S x H (biases already folded in)
            float* __restrict__ Hout,        // S x H; reads t-1, writes t
            int* cnt,                        // [S] arrival counters
            int wait_target)                 // 128*(layer+1)
{
    extern __shared__ float smem[];
    float* sW = smem;                         // ROWS_PER_CTA * H_DIM floats

    const int tid  = threadIdx.x;
    const int lane = tid & 31;
    const int warp = tid >> 5;
    const int row0 = blockIdx.x * ROWS_PER_CTA;

    // Stage this CTA's 16 weight rows into SMEM (contiguous rows, coalesced)
    {
        const float4* Wg  = (const float4*)(Wh + (size_t)row0 * H_DIM);
        float4* sW4 = (float4*)sW;
        const int nvec = ROWS_PER_CTA * H_DIM / 4;
        for (int i = tid; i < nvec; i += SCAN_THREADS) sW4[i] = Wg[i];
    }
    __syncthreads();

    const float4* w0 = (const float4*)(sW + (warp * 4 + 0) * H_DIM);
    const float4* w1 = (const float4*)(sW + (warp * 4 + 1) * H_DIM);
    const float4* w2 = (const float4*)(sW + (warp * 4 + 2) * H_DIM);
    const float4* w3 = (const float4*)(sW + (warp * 4 + 3) * H_DIM);

    const int gr = row0 + warp * 4 + lane;    // output row for lanes 0..3

    for (int t = 0; t < S_LEN; t++) {
        // U is stable data (produced by the preceding GEMM) — load before poll
        float uval = 0.f;
        if (lane < 4) uval = __ldg(U + (size_t)t * H_DIM + gr);

        float a0 = 0.f, a1 = 0.f, a2 = 0.f, a3 = 0.f;

        if (t > 0) {
            // All threads poll (one coalesced L2 request per warp per probe)
            while (ld_relaxed_gpu(cnt + (t - 1)) < wait_target) { }
            fence_gpu();   // acquire side of the handshake

            // 4 rows per warp; h(t-1) streamed from L2 with 2-deep prefetch
            const float4* hp4 = (const float4*)(Hout + (size_t)(t - 1) * H_DIM);
            float4 h0 = __ldcg(hp4 + lane);
            float4 h1 = __ldcg(hp4 + lane + 32);
#pragma unroll
            for (int i = 0; i < H_DIM / 128; i++) {
                const int idx = lane + 32 * i;
                float4 hn;
                if (i + 2 < H_DIM / 128) hn = __ldcg(hp4 + idx + 64);
                float4 x0 = w0[idx];
                float4 x1 = w1[idx];
                float4 x2 = w2[idx];
                float4 x3 = w3[idx];
                a0 += x0.x * h0.x + x0.y * h0.y + x0.z * h0.z + x0.w * h0.w;
                a1 += x1.x * h0.x + x1.y * h0.y + x1.z * h0.z + x1.w * h0.w;
                a2 += x2.x * h0.x + x2.y * h0.y + x2.z * h0.z + x2.w * h0.w;
                a3 += x3.x * h0.x + x3.y * h0.y + x3.z * h0.z + x3.w * h0.w;
                h0 = h1;
                h1 = hn;
            }
#pragma unroll
            for (int off = 16; off > 0; off >>= 1) {
                a0 += __shfl_xor_sync(0xffffffffu, a0, off);
                a1 += __shfl_xor_sync(0xffffffffu, a1, off);
                a2 += __shfl_xor_sync(0xffffffffu, a2, off);
                a3 += __shfl_xor_sync(0xffffffffu, a3, off);
            }
        }

        // After xor-reduction every lane holds the full sums; lanes 0..3 commit.
        // CRITICAL: the release fence is executed by the STORING thread
        // (orders ITS store to gpu scope) before the barrier — R2-proven.
        if (lane < 4) {
            float accv = (lane == 0) ? a0 : (lane == 1) ? a1 : (lane == 2) ? a2 : a3;
            __stcg(Hout + (size_t)t * H_DIM + gr, tanhf(uval + accv));
            fence_gpu();
        }
        __syncthreads();              // all stores+fences happen-before arrive
        if (tid == 0) red_add_gpu(cnt + t);
    }
}

// ---------------------------------------------------------------------------
extern "C" void kernel_launch(void* const* d_in, const int* in_sizes, int n_in,
                              void* d_out, int out_size)
{
    const float* input = (const float*)d_in[0];   // (1, S, I)
    const float* Wi0   = (const float*)d_in[1];   // (H, I)
    const float* bi0   = (const float*)d_in[2];   // (H)
    const float* WiR   = (const float*)d_in[3];   // (L-1, H, H)
    const float* biR   = (const float*)d_in[4];   // (L-1, H)
    const float* Wh    = (const float*)d_in[5];   // (L, H, H)
    const float* bh    = (const float*)d_in[6];   // (L, H)
    float* out = (float*)d_out;                   // (S, 1, H) contiguous

    float *U, *HA; int* cnt;
    cudaGetSymbolAddress((void**)&U,  g_U);
    cudaGetSymbolAddress((void**)&HA, g_HA);
    cudaGetSymbolAddress((void**)&cnt, g_cnt);

    cudaFuncSetAttribute(scan_kernel,
                         cudaFuncAttributeMaxDynamicSharedMemorySize,
                         SCAN_SMEM_BYTES);

    // Counters must be zero at the start of every replay (graph-captured node)
    cudaMemsetAsync(cnt, 0, S_LEN * sizeof(int));

    dim3 gemm_grid(H_DIM / 128, S_LEN / 128);   // (16, 8)

    // Layer 0: U = X @ Wi0^T + bi0 + bh[0]; then scan with Wh[0]
    gemm_bias_kernel<<<gemm_grid, 256>>>(input, Wi0, U, bi0, bh, S_LEN, H_DIM, I_DIM);
    scan_kernel<<<SCAN_CTAS, SCAN_THREADS, SCAN_SMEM_BYTES>>>(Wh, U, HA, cnt, SCAN_CTAS);

    // Layers 1..3
    for (int l = 1; l < L_NUM; l++) {
        const float* Wi_l = WiR + (size_t)(l - 1) * H_DIM * H_DIM;
        const float* bi_l = biR + (size_t)(l - 1) * H_DIM;
        const float* Wh_l = Wh  + (size_t)l * H_DIM * H_DIM;
        const float* bh_l = bh  + (size_t)l * H_DIM;
        float* dst = (l == L_NUM - 1) ? out : HA;

        gemm_bias_kernel<<<gemm_grid, 256>>>(HA, Wi_l, U, bi_l, bh_l,
                                             S_LEN, H_DIM, H_DIM);
        scan_kernel<<<SCAN_CTAS, SCAN_THREADS, SCAN_SMEM_BYTES>>>(Wh_l, U, dst,
                                                                  cnt, SCAN_CTAS * (l + 1));
    }
}

// round 6
// speedup vs baseline: 1.2229x; 1.2229x over previous
#include <cuda_runtime.h>
#include <math.h>

// Problem constants (fixed by the reference)
#define S_LEN   1024
#define I_DIM   1024
#define H_DIM   2048
#define L_NUM   4

#define SCAN_CTAS     128
#define ROWS_PER_CTA  16              // H_DIM / SCAN_CTAS
#define SCAN_THREADS  128             // 4 warps, 4 rows per warp
#define SCAN_SMEM_BYTES (ROWS_PER_CTA * H_DIM * (int)sizeof(float))  // 131072 (weights only)
#define CNT_STRIDE 32                 // 128B between per-step counters (slice decorrelation)
#define ARRIVALS_PER_STEP (SCAN_CTAS * 4)   // one red per warp per CTA = 512

// Scratch (device globals — no allocation allowed)
__device__ float g_U [S_LEN * H_DIM];            // u_l(t) for current layer (8 MB)
__device__ float g_HA[S_LEN * H_DIM];            // hidden states of current layer (8 MB)
__device__ int   g_cnt[S_LEN * CNT_STRIDE];      // strided per-timestep arrival counters

// ---------------------------------------------------------------------------
// Memory-model helpers. Release is folded into the arrival red; the consumer
// polls with an acquiring load. gpu-scope edge (producer red.release ->
// warp0 ld.acquire) composes with a cta-scope edge (warp0 st.release.cta on
// the SMEM flag -> other warps ld.acquire.cta) by PTX causality.
// ---------------------------------------------------------------------------
__device__ __forceinline__ int ld_acquire_gpu(const int* p) {
    int v;
    asm volatile("ld.acquire.gpu.global.s32 %0, [%1];" : "=r"(v) : "l"(p) : "memory");
    return v;
}
__device__ __forceinline__ void red_release_gpu(int* p) {
    asm volatile("red.release.gpu.global.add.s32 [%0], 1;" :: "l"(p) : "memory");
}
__device__ __forceinline__ void st_release_shared(int* p, int v) {
    unsigned a = (unsigned)__cvta_generic_to_shared(p);
    asm volatile("st.release.cta.shared.s32 [%0], %1;" :: "r"(a), "r"(v) : "memory");
}
__device__ __forceinline__ int ld_acquire_shared(const int* p) {
    unsigned a = (unsigned)__cvta_generic_to_shared(p);
    int v;
    asm volatile("ld.acquire.cta.shared.s32 %0, [%1];" : "=r"(v) : "r"(a) : "memory");
    return v;
}

// ---------------------------------------------------------------------------
// GEMM: C[M,N] = A[M,K] @ B[N,K]^T + bias1[n] + bias2[n]
// 128x128 tile, BK=8, 256 threads, 8x8 per-thread microtile. (Proven; unchanged.)
// ---------------------------------------------------------------------------
__global__ void gemm_bias_kernel(const float* __restrict__ A,
                                 const float* __restrict__ B,
                                 float* __restrict__ C,
                                 const float* __restrict__ bias1,
                                 const float* __restrict__ bias2,
                                 int M, int N, int K)
{
    __shared__ float As[8][128];
    __shared__ float Bs[8][128];

    const int tid = threadIdx.x;
    const int bm  = blockIdx.y * 128;
    const int bn  = blockIdx.x * 128;

    const int loadRow = tid >> 1;        // 0..127
    const int loadCol = (tid & 1) * 4;   // 0 or 4

    const int tx = tid & 15;             // n sub-tile
    const int ty = tid >> 4;             // m sub-tile

    float acc[8][8];
#pragma unroll
    for (int i = 0; i < 8; i++)
#pragma unroll
        for (int j = 0; j < 8; j++) acc[i][j] = 0.f;

    const float* Ag = A + (size_t)(bm + loadRow) * K + loadCol;
    const float* Bg = B + (size_t)(bn + loadRow) * K + loadCol;

    for (int k0 = 0; k0 < K; k0 += 8) {
        float4 av = *(const float4*)(Ag + k0);
        float4 bv = *(const float4*)(Bg + k0);
        As[loadCol + 0][loadRow] = av.x;
        As[loadCol + 1][loadRow] = av.y;
        As[loadCol + 2][loadRow] = av.z;
        As[loadCol + 3][loadRow] = av.w;
        Bs[loadCol + 0][loadRow] = bv.x;
        Bs[loadCol + 1][loadRow] = bv.y;
        Bs[loadCol + 2][loadRow] = bv.z;
        Bs[loadCol + 3][loadRow] = bv.w;
        __syncthreads();

#pragma unroll
        for (int k = 0; k < 8; k++) {
            float a[8], b[8];
#pragma unroll
            for (int i = 0; i < 8; i++) a[i] = As[k][ty * 8 + i];
#pragma unroll
            for (int j = 0; j < 8; j++) b[j] = Bs[k][tx * 8 + j];
#pragma unroll
            for (int i = 0; i < 8; i++)
#pragma unroll
                for (int j = 0; j < 8; j++)
                    acc[i][j] += a[i] * b[j];
        }
        __syncthreads();
    }

    // Epilogue with fused bias add, float4 stores
#pragma unroll
    for (int i = 0; i < 8; i++) {
        const int m = bm + ty * 8 + i;
        float* crow = C + (size_t)m * N + bn + tx * 8;
#pragma unroll
        for (int j = 0; j < 8; j += 4) {
            const int n = bn + tx * 8 + j;
            float4 v;
            v.x = acc[i][j + 0] + bias1[n + 0] + bias2[n + 0];
            v.y = acc[i][j + 1] + bias1[n + 1] + bias2[n + 1];
            v.z = acc[i][j + 2] + bias1[n + 2] + bias2[n + 2];
            v.w = acc[i][j + 3] + bias1[n + 3] + bias2[n + 3];
            *(float4*)(crow + j) = v;
        }
    }
}

// ---------------------------------------------------------------------------
// Persistent scan: h(t) = tanh(U[t] + Wh @ h(t-1)) over t = 0..S-1.
// Wh (H x H) sliced across 128 CTAs' SMEM (16 rows each, 4 rows per warp).
// Per step, per warp (NO intra-CTA barriers in the loop):
//   wait:   warp0 polls cnt[t-1] with ld.acquire.gpu (one coalesced request),
//           then relays via SMEM flag (st.release.cta); warps 1-3 spin on the
//           flag with ld.acquire.cta (zero L2 traffic).
//   load:   h(t-1) streamed from L2 via depth-8 __ldcg register pipeline,
//           fully hiding L2 latency under the SMEM weight stream.
//   commit: lane0 stores its warp's 4 contiguous rows (st.cg.v4) and does
//           red.release.gpu.add on cnt[t]. 512 arrivals per step.
// ---------------------------------------------------------------------------
__global__ void __launch_bounds__(SCAN_THREADS, 1)
scan_kernel(const float* __restrict__ Wh,    // layer's H x H row-major slice base
            const float* __restrict__ U,     // S x H (biases already folded in)
            float* __restrict__ Hout,        // S x H; reads t-1, writes t
            int* cnt,                        // strided arrival counters
            int wait_target)                 // 512*(layer+1)
{
    extern __shared__ float smem[];
    float* sW = smem;                         // ROWS_PER_CTA * H_DIM floats
    __shared__ int s_flag;                    // intra-CTA step relay

    const int tid  = threadIdx.x;
    const int lane = tid & 31;
    const int warp = tid >> 5;
    const int row0 = blockIdx.x * ROWS_PER_CTA;

    // Stage this CTA's 16 weight rows into SMEM (contiguous rows, coalesced)
    {
        const float4* Wg  = (const float4*)(Wh + (size_t)row0 * H_DIM);
        float4* sW4 = (float4*)sW;
        const int nvec = ROWS_PER_CTA * H_DIM / 4;
        for (int i = tid; i < nvec; i += SCAN_THREADS) sW4[i] = Wg[i];
    }
    if (tid == 0) s_flag = -1;
    __syncthreads();

    const float4* w0 = (const float4*)(sW + (warp * 4 + 0) * H_DIM);
    const float4* w1 = (const float4*)(sW + (warp * 4 + 1) * H_DIM);
    const float4* w2 = (const float4*)(sW + (warp * 4 + 2) * H_DIM);
    const float4* w3 = (const float4*)(sW + (warp * 4 + 3) * H_DIM);

    const int gr0 = row0 + warp * 4;          // this warp's first output row

    for (int t = 0; t < S_LEN; t++) {
        // U is stable data (from the preceding GEMM) — prefetch before wait
        float4 uv;
        if (lane == 0) uv = __ldg((const float4*)(U + (size_t)t * H_DIM + gr0));

        float a0 = 0.f, a1 = 0.f, a2 = 0.f, a3 = 0.f;

        if (t > 0) {
            if (warp == 0) {
                // All lanes poll the same address -> one L2 request per probe
                const int* cp = cnt + (size_t)(t - 1) * CNT_STRIDE;
                while (ld_acquire_gpu(cp) < wait_target) { }
                if (lane == 0) st_release_shared(&s_flag, t);
            } else {
                while (ld_acquire_shared(&s_flag) < t) { }
            }

            // h(t-1): depth-8 register-rolling __ldcg pipeline
            const float4* hp4 = (const float4*)(Hout + (size_t)(t - 1) * H_DIM);
            float4 hb[8];
#pragma unroll
            for (int p = 0; p < 8; p++) hb[p] = __ldcg(hp4 + lane + 32 * p);

#pragma unroll
            for (int i = 0; i < H_DIM / 128; i++) {     // 16 iterations
                const int idx = lane + 32 * i;
                float4 hv = hb[i & 7];
                if (i + 8 < H_DIM / 128)
                    hb[i & 7] = __ldcg(hp4 + idx + 32 * 8);
                float4 x0 = w0[idx];
                float4 x1 = w1[idx];
                float4 x2 = w2[idx];
                float4 x3 = w3[idx];
                a0 += x0.x * hv.x + x0.y * hv.y + x0.z * hv.z + x0.w * hv.w;
                a1 += x1.x * hv.x + x1.y * hv.y + x1.z * hv.z + x1.w * hv.w;
                a2 += x2.x * hv.x + x2.y * hv.y + x2.z * hv.z + x2.w * hv.w;
                a3 += x3.x * hv.x + x3.y * hv.y + x3.z * hv.z + x3.w * hv.w;
            }
#pragma unroll
            for (int off = 16; off > 0; off >>= 1) {
                a0 += __shfl_xor_sync(0xffffffffu, a0, off);
                a1 += __shfl_xor_sync(0xffffffffu, a1, off);
                a2 += __shfl_xor_sync(0xffffffffu, a2, off);
                a3 += __shfl_xor_sync(0xffffffffu, a3, off);
            }
        }

        // lane0 holds all four reduced sums: one st.cg.v4 + release-red arrive
        if (lane == 0) {
            float4 hv;
            hv.x = tanhf(uv.x + a0);
            hv.y = tanhf(uv.y + a1);
            hv.z = tanhf(uv.z + a2);
            hv.w = tanhf(uv.w + a3);
            __stcg((float4*)(Hout + (size_t)t * H_DIM + gr0), hv);
            red_release_gpu(cnt + (size_t)t * CNT_STRIDE);
        }
    }
}

// ---------------------------------------------------------------------------
extern "C" void kernel_launch(void* const* d_in, const int* in_sizes, int n_in,
                              void* d_out, int out_size)
{
    const float* input = (const float*)d_in[0];   // (1, S, I)
    const float* Wi0   = (const float*)d_in[1];   // (H, I)
    const float* bi0   = (const float*)d_in[2];   // (H)
    const float* WiR   = (const float*)d_in[3];   // (L-1, H, H)
    const float* biR   = (const float*)d_in[4];   // (L-1, H)
    const float* Wh    = (const float*)d_in[5];   // (L, H, H)
    const float* bh    = (const float*)d_in[6];   // (L, H)
    float* out = (float*)d_out;                   // (S, 1, H) contiguous

    float *U, *HA; int* cnt;
    cudaGetSymbolAddress((void**)&U,  g_U);
    cudaGetSymbolAddress((void**)&HA, g_HA);
    cudaGetSymbolAddress((void**)&cnt, g_cnt);

    cudaFuncSetAttribute(scan_kernel,
                         cudaFuncAttributeMaxDynamicSharedMemorySize,
                         SCAN_SMEM_BYTES);

    // Counters must be zero at the start of every replay (graph-captured node)
    cudaMemsetAsync(cnt, 0, S_LEN * CNT_STRIDE * sizeof(int));

    dim3 gemm_grid(H_DIM / 128, S_LEN / 128);   // (16, 8)

    // Layer 0: U = X @ Wi0^T + bi0 + bh[0]; then scan with Wh[0]
    gemm_bias_kernel<<<gemm_grid, 256>>>(input, Wi0, U, bi0, bh, S_LEN, H_DIM, I_DIM);
    scan_kernel<<<SCAN_CTAS, SCAN_THREADS, SCAN_SMEM_BYTES>>>(Wh, U, HA, cnt,
                                                              ARRIVALS_PER_STEP);

    // Layers 1..3
    for (int l = 1; l < L_NUM; l++) {
        const float* Wi_l = WiR + (size_t)(l - 1) * H_DIM * H_DIM;
        const float* bi_l = biR + (size_t)(l - 1) * H_DIM;
        const float* Wh_l = Wh  + (size_t)l * H_DIM * H_DIM;
        const float* bh_l = bh  + (size_t)l * H_DIM;
        float* dst = (l == L_NUM - 1) ? out : HA;

        gemm_bias_kernel<<<gemm_grid, 256>>>(HA, Wi_l, U, bi_l, bh_l,
                                             S_LEN, H_DIM, H_DIM);
        scan_kernel<<<SCAN_CTAS, SCAN_THREADS, SCAN_SMEM_BYTES>>>(Wh_l, U, dst, cnt,
                                                                  ARRIVALS_PER_STEP * (l + 1));
    }
}